// round 2
// baseline (speedup 1.0000x reference)
#include <cuda_runtime.h>
#include <math.h>

#define SEQ     2048
#define HIDDEN  4096
#define NHEADS  32
#define HD      128
#define QKV_N   (3 * HIDDEN)   // 12288
#define ROWLEN  QKV_N          // mixed row stride

// ---------------------------------------------------------------------------
// Scratch (static device globals; allocation inside kernel_launch is banned)
// ---------------------------------------------------------------------------
__device__ float g_mixed[SEQ * QKV_N];                       // 100.7 MB
__device__ float g_scores[(long long)NHEADS * SEQ * SEQ];    // 512 MB
__device__ float g_ctx[SEQ * HIDDEN];                        // 33.6 MB

// ---------------------------------------------------------------------------
// Generic 128x128x8 SGEMM, 256 threads, 8x8 register tile.
//  BT     : B given as N x K row-major (compute A @ B^T)
//  BIAS   : add bias[col]
//  CMASK  : causal mask epilogue (col > row -> -10000), with fully-masked-tile
//           early out
//  CAUSALK: limit K loop to rowBase+BM (for P@V where P is lower-triangular)
// z-dimension handles per-head batching via element strides.
// ---------------------------------------------------------------------------
template <bool BT, bool BIAS, bool CMASK, bool CAUSALK>
__global__ void __launch_bounds__(256)
sgemm_kernel(const float* __restrict__ A, const float* __restrict__ B,
             const float* __restrict__ bias, float* __restrict__ C,
             int M, int N, int K, int lda, int ldb, int ldc,
             long long strideAz, long long strideBz, long long strideCz,
             float alpha)
{
    constexpr int BM = 128, BN = 128, BK = 8;
    __shared__ float As[BK][BM];
    __shared__ float Bs[BK][BN];

    const int z = blockIdx.z;
    A += (long long)z * strideAz;
    B += (long long)z * strideBz;
    C += (long long)z * strideCz;

    const int rowBase = blockIdx.y * BM;
    const int colBase = blockIdx.x * BN;
    const int tid = threadIdx.x;
    const int tx = tid & 15;   // 0..15 (col group)
    const int ty = tid >> 4;   // 0..15 (row group)

    if (CMASK && colBase > rowBase + BM - 1) {
        const float4 mv = make_float4(-10000.f, -10000.f, -10000.f, -10000.f);
        #pragma unroll
        for (int i = 0; i < 8; i++) {
            const int r = rowBase + ty * 8 + i;
            float* cp = &C[(long long)r * ldc + colBase + tx * 8];
            *(float4*)(cp)     = mv;
            *(float4*)(cp + 4) = mv;
        }
        return;
    }

    const int kEnd = CAUSALK ? min(K, rowBase + BM) : K;

    const int aRow = tid >> 1;          // 0..127
    const int aCol = (tid & 1) * 4;     // 0 or 4  (k within BK)
    const int bRow = tid >> 5;          // 0..7    (k within BK, NN case)
    const int bCol = (tid & 31) * 4;    // 0..124  (n, NN case)

    float acc[8][8] = {};

    for (int k0 = 0; k0 < kEnd; k0 += BK) {
        const float4 av =
            *(const float4*)&A[(long long)(rowBase + aRow) * lda + k0 + aCol];
        As[aCol + 0][aRow] = av.x;
        As[aCol + 1][aRow] = av.y;
        As[aCol + 2][aRow] = av.z;
        As[aCol + 3][aRow] = av.w;

        if (BT) {
            const float4 bv =
                *(const float4*)&B[(long long)(colBase + aRow) * ldb + k0 + aCol];
            Bs[aCol + 0][aRow] = bv.x;
            Bs[aCol + 1][aRow] = bv.y;
            Bs[aCol + 2][aRow] = bv.z;
            Bs[aCol + 3][aRow] = bv.w;
        } else {
            const float4 bv =
                *(const float4*)&B[(long long)(k0 + bRow) * ldb + colBase + bCol];
            *(float4*)&Bs[bRow][bCol] = bv;
        }
        __syncthreads();

        #pragma unroll
        for (int k = 0; k < BK; k++) {
            const float4 a0 = *(const float4*)&As[k][ty * 8];
            const float4 a1 = *(const float4*)&As[k][ty * 8 + 4];
            const float4 b0 = *(const float4*)&Bs[k][tx * 8];
            const float4 b1 = *(const float4*)&Bs[k][tx * 8 + 4];
            const float a[8] = {a0.x, a0.y, a0.z, a0.w, a1.x, a1.y, a1.z, a1.w};
            const float b[8] = {b0.x, b0.y, b0.z, b0.w, b1.x, b1.y, b1.z, b1.w};
            #pragma unroll
            for (int i = 0; i < 8; i++)
                #pragma unroll
                for (int j = 0; j < 8; j++)
                    acc[i][j] = fmaf(a[i], b[j], acc[i][j]);
        }
        __syncthreads();
    }

    #pragma unroll
    for (int i = 0; i < 8; i++) {
        const int r = rowBase + ty * 8 + i;
        #pragma unroll
        for (int jj = 0; jj < 2; jj++) {
            const int c = colBase + tx * 8 + jj * 4;
            float4 v;
            v.x = acc[i][jj * 4 + 0] * alpha;
            v.y = acc[i][jj * 4 + 1] * alpha;
            v.z = acc[i][jj * 4 + 2] * alpha;
            v.w = acc[i][jj * 4 + 3] * alpha;
            if (BIAS) {
                v.x += bias[c + 0];
                v.y += bias[c + 1];
                v.z += bias[c + 2];
                v.w += bias[c + 3];
            }
            if (CMASK) {
                if (c + 0 > r) v.x = -10000.f;
                if (c + 1 > r) v.y = -10000.f;
                if (c + 2 > r) v.z = -10000.f;
                if (c + 3 > r) v.w = -10000.f;
            }
            *(float4*)&C[(long long)r * ldc + c] = v;
        }
    }
}

// ---------------------------------------------------------------------------
// RoPE on first ROT=32 dims of q and k (in place in mixed buffer).
// ---------------------------------------------------------------------------
__global__ void rope_kernel(float* __restrict__ mixed)
{
    const int idx = blockIdx.x * blockDim.x + threadIdx.x;
    const int i  = idx & 15;
    const int qk = (idx >> 4) & 1;
    const int h  = (idx >> 5) & 31;
    const int s  = idx >> 10;
    if (s >= SEQ) return;

    const double invd = pow(10000.0, -(double)i / 16.0);
    const float freq = (float)s * (float)invd;     // float32 phase like jax
    const double fd = (double)freq;
    const float c  = (float)cos(fd);
    const float sn = (float)sin(fd);

    float* p = mixed + (long long)s * ROWLEN + h * 384 + qk * HD;
    const float x1 = p[i];
    const float x2 = p[i + 16];
    p[i]      = x1 * c - x2 * sn;
    p[i + 16] = x2 * c + x1 * sn;
}

// ---------------------------------------------------------------------------
// Row softmax over 2048 columns. One 256-thread block per row.
// ---------------------------------------------------------------------------
__device__ __forceinline__ float warpMax(float v) {
    #pragma unroll
    for (int o = 16; o; o >>= 1) v = fmaxf(v, __shfl_xor_sync(0xffffffffu, v, o));
    return v;
}
__device__ __forceinline__ float warpSum(float v) {
    #pragma unroll
    for (int o = 16; o; o >>= 1) v += __shfl_xor_sync(0xffffffffu, v, o);
    return v;
}

__global__ void __launch_bounds__(256) softmax_kernel(float* __restrict__ S)
{
    float* p = S + (long long)blockIdx.x * SEQ;
    const int tid = threadIdx.x;
    const int lane = tid & 31, warp = tid >> 5;
    __shared__ float red[8];

    float v[8];
    float m = -1e30f;
    #pragma unroll
    for (int j = 0; j < 8; j++) {
        v[j] = p[tid + j * 256];
        m = fmaxf(m, v[j]);
    }
    m = warpMax(m);
    if (lane == 0) red[warp] = m;
    __syncthreads();
    if (warp == 0) {
        float t = red[lane & 7];      // replication is fine for max
        t = warpMax(t);
        if (lane == 0) red[0] = t;
    }
    __syncthreads();
    m = red[0];

    float sum = 0.f;
    #pragma unroll
    for (int j = 0; j < 8; j++) {
        v[j] = expf(v[j] - m);
        sum += v[j];
    }
    sum = warpSum(sum);
    __syncthreads();
    if (lane == 0) red[warp] = sum;
    __syncthreads();
    if (warp == 0) {
        float t = (lane < 8) ? red[lane] : 0.f;   // FIX: no 4x replication in sum
        t = warpSum(t);
        if (lane == 0) red[0] = t;
    }
    __syncthreads();
    const float inv = 1.f / red[0];

    #pragma unroll
    for (int j = 0; j < 8; j++) p[tid + j * 256] = v[j] * inv;
}

// ---------------------------------------------------------------------------
// Launcher
// ---------------------------------------------------------------------------
extern "C" void kernel_launch(void* const* d_in, const int* in_sizes, int n_in,
                              void* d_out, int out_size)
{
    const float* hidden  = (const float*)d_in[0];
    const float* W_qkv   = (const float*)d_in[2];
    const float* b_qkv   = (const float*)d_in[3];
    const float* W_dense = (const float*)d_in[4];
    const float* b_dense = (const float*)d_in[5];
    float* out = (float*)d_out;

    float *mixed, *scores, *ctx;
    cudaGetSymbolAddress((void**)&mixed,  g_mixed);
    cudaGetSymbolAddress((void**)&scores, g_scores);
    cudaGetSymbolAddress((void**)&ctx,    g_ctx);

    const float inv_sqrt_hd = 0.08838834764831845f;  // 1/sqrt(128)

    // 1) QKV projection: mixed = hidden @ W_qkv + b_qkv   [2048 x 12288]
    sgemm_kernel<false, true, false, false>
        <<<dim3(QKV_N / 128, SEQ / 128, 1), 256>>>(
            hidden, W_qkv, b_qkv, mixed,
            SEQ, QKV_N, HIDDEN, HIDDEN, QKV_N, QKV_N, 0, 0, 0, 1.f);

    // 2) RoPE in place on q,k rot dims
    rope_kernel<<<(SEQ * NHEADS * 2 * 16) / 256, 256>>>(mixed);

    // 3) scores[h] = (Q_h @ K_h^T) / sqrt(HD), causal-masked to -10000
    sgemm_kernel<true, false, true, false>
        <<<dim3(SEQ / 128, SEQ / 128, NHEADS), 256>>>(
            mixed, mixed + HD, nullptr, scores,
            SEQ, SEQ, HD, ROWLEN, ROWLEN, SEQ,
            384, 384, (long long)SEQ * SEQ, inv_sqrt_hd);

    // 4) row softmax
    softmax_kernel<<<NHEADS * SEQ, 256>>>(scores);

    // 5) ctx[h] = P_h @ V_h  (K loop limited to causal extent)
    sgemm_kernel<false, false, false, true>
        <<<dim3(1, SEQ / 128, NHEADS), 256>>>(
            scores, mixed + 2 * HD, nullptr, ctx,
            SEQ, HD, SEQ, SEQ, ROWLEN, HIDDEN,
            (long long)SEQ * SEQ, 384, HD, 1.f);

    // 6) output = ctx @ W_dense + b_dense
    sgemm_kernel<false, true, false, false>
        <<<dim3(HIDDEN / 128, SEQ / 128, 1), 256>>>(
            ctx, W_dense, b_dense, out,
            SEQ, HIDDEN, HIDDEN, HIDDEN, HIDDEN, HIDDEN, 0, 0, 0, 1.f);
}

// round 4
// speedup vs baseline: 2.1385x; 2.1385x over previous
#include <cuda_runtime.h>
#include <cuda_bf16.h>
#include <math.h>
#include <stdint.h>

#define SEQ     2048
#define HIDDEN  4096
#define NHEADS  32
#define HD      128
#define QKV_N   12288

// ---------------------------------------------------------------------------
// Scratch (device globals; no allocation allowed in kernel_launch)
// ---------------------------------------------------------------------------
__device__ float g_mixed[SEQ * QKV_N];
__device__ float g_scores[(long long)NHEADS * SEQ * SEQ];
__device__ float g_ctx[SEQ * HIDDEN];

__device__ __align__(256) __nv_bfloat16 g_hidHi[SEQ * HIDDEN];
__device__ __align__(256) __nv_bfloat16 g_hidLo[SEQ * HIDDEN];
__device__ __align__(256) __nv_bfloat16 g_wqkvHi[(long long)QKV_N * HIDDEN]; // W_qkv^T [n][k]
__device__ __align__(256) __nv_bfloat16 g_wqkvLo[(long long)QKV_N * HIDDEN];
__device__ __align__(256) __nv_bfloat16 g_qHi[NHEADS * SEQ * HD];
__device__ __align__(256) __nv_bfloat16 g_qLo[NHEADS * SEQ * HD];
__device__ __align__(256) __nv_bfloat16 g_kHi[NHEADS * SEQ * HD];
__device__ __align__(256) __nv_bfloat16 g_kLo[NHEADS * SEQ * HD];
__device__ __align__(256) __nv_bfloat16 g_vtHi[NHEADS * HD * SEQ];          // V^T [h][d][t]
__device__ __align__(256) __nv_bfloat16 g_vtLo[NHEADS * HD * SEQ];
__device__ __align__(256) __nv_bfloat16 g_pHi[(long long)NHEADS * SEQ * SEQ];
__device__ __align__(256) __nv_bfloat16 g_pLo[(long long)NHEADS * SEQ * SEQ];
__device__ __align__(256) __nv_bfloat16 g_ctxHi[SEQ * HIDDEN];
__device__ __align__(256) __nv_bfloat16 g_ctxLo[SEQ * HIDDEN];
__device__ __align__(256) __nv_bfloat16 g_wdHi[HIDDEN * HIDDEN];            // W_dense^T
__device__ __align__(256) __nv_bfloat16 g_wdLo[HIDDEN * HIDDEN];

// ---------------------------------------------------------------------------
// Helpers (all plain sm_80-class PTX: cp.async + mma.sync — no 'a' features)
// ---------------------------------------------------------------------------
__device__ __forceinline__ uint32_t smem_u32(const void* p) {
    uint32_t a;
    asm("{ .reg .u64 t; cvta.to.shared.u64 t, %1; cvt.u32.u64 %0, t; }" : "=r"(a) : "l"(p));
    return a;
}
#define CPA16(dst, src)  asm volatile("cp.async.cg.shared.global [%0], [%1], 16;" :: "r"(dst), "l"(src))
#define CP_COMMIT()      asm volatile("cp.async.commit_group;" ::: "memory")
#define CP_WAIT1()       asm volatile("cp.async.wait_group 1;" ::: "memory")
#define CP_WAIT0()       asm volatile("cp.async.wait_group 0;" ::: "memory")

#define MMA(d, a, b)                                                          \
    asm volatile("mma.sync.aligned.m16n8k16.row.col.f32.bf16.bf16.f32 "       \
        "{%0,%1,%2,%3}, {%4,%5,%6,%7}, {%8,%9}, {%0,%1,%2,%3};"               \
        : "+f"((d)[0]), "+f"((d)[1]), "+f"((d)[2]), "+f"((d)[3])              \
        : "r"((a)[0]), "r"((a)[1]), "r"((a)[2]), "r"((a)[3]),                 \
          "r"((b)[0]), "r"((b)[1]))

// SMEM geometry: 4 planes (Ahi, Alo, Bhi, Blo) x 128 rows x 32 bf16, padded
// to 40 bf16 (80B) per row => conflict-free fragment LDS. Double buffered.
#define ROW_W     20                 // words (u32) per row
#define PLANE_W   (128 * ROW_W)      // 2560 words = 10240 B
#define STAGE_B   (4 * PLANE_W * 4)  // 40960 B
#define SMEM_TOTAL (2 * STAGE_B)     // 81920 B

// ---------------------------------------------------------------------------
// Split-bf16 GEMM via mma.sync: C[M,N] = alpha * A[M,K] @ B[N,K]^T (+bias)
// ---------------------------------------------------------------------------
template <bool BIAS, bool CAUSALK, bool SKIPUPPER>
__global__ void __launch_bounds__(256, 1)
mma_gemm(const __nv_bfloat16* __restrict__ Ahi, const __nv_bfloat16* __restrict__ Alo,
         const __nv_bfloat16* __restrict__ Bhi, const __nv_bfloat16* __restrict__ Blo,
         const float* __restrict__ bias, float* __restrict__ C,
         int K, int lda, int ldb, int ldc,
         long long azs, long long bzs, long long czs, float alpha)
{
    extern __shared__ char smem[];
    const int tid = threadIdx.x;
    const int rowBase = blockIdx.y * 128;
    const int colBase = blockIdx.x * 128;
    if (SKIPUPPER && colBase > rowBase) return;

    const int z = blockIdx.z;
    Ahi += (long long)z * azs;  Alo += (long long)z * azs;
    Bhi += (long long)z * bzs;  Blo += (long long)z * bzs;
    C   += (long long)z * czs;

    const int kEnd  = CAUSALK ? min(K, rowBase + 128) : K;
    const int niter = kEnd >> 5;

    const uint32_t sbase = smem_u32(smem);
    const uint32_t* sw = (const uint32_t*)smem;

    const int lane = tid & 31;
    const int wid  = tid >> 5;
    const int wm   = wid & 1;    // 0..1  -> 64-row slice
    const int wn   = wid >> 1;   // 0..3  -> 32-col slice

    float acc[4][4][4] = {};

    // 2048 x 16B chunks per stage, 8 per thread
    auto issue = [&](int s, int k0) {
        #pragma unroll
        for (int j = 0; j < 8; j++) {
            const int c     = j * 256 + tid;
            const int plane = c >> 9;
            const int rem   = c & 511;
            const int row   = rem >> 2;
            const int seg   = rem & 3;
            const uint32_t dst = sbase + (uint32_t)(s * 4 + plane) * 10240u
                               + (uint32_t)row * 80u + (uint32_t)seg * 16u;
            const __nv_bfloat16* src;
            if (plane == 0)      src = Ahi + (long long)(rowBase + row) * lda + k0 + seg * 8;
            else if (plane == 1) src = Alo + (long long)(rowBase + row) * lda + k0 + seg * 8;
            else if (plane == 2) src = Bhi + (long long)(colBase + row) * ldb + k0 + seg * 8;
            else                 src = Blo + (long long)(colBase + row) * ldb + k0 + seg * 8;
            CPA16(dst, src);
        }
        CP_COMMIT();
    };

    issue(0, 0);

    for (int i = 0; i < niter; i++) {
        const int s = i & 1;
        if (i + 1 < niter) { issue(s ^ 1, (i + 1) << 5); CP_WAIT1(); }
        else               { CP_WAIT0(); }
        __syncthreads();

        const uint32_t* pAh = sw + (s * 4 + 0) * PLANE_W;
        const uint32_t* pAl = sw + (s * 4 + 1) * PLANE_W;
        const uint32_t* pBh = sw + (s * 4 + 2) * PLANE_W;
        const uint32_t* pBl = sw + (s * 4 + 3) * PLANE_W;

        #pragma unroll
        for (int kk = 0; kk < 2; kk++) {
            const int wc = kk * 8 + (lane & 3);
            uint32_t ah[4][4], al[4][4], bh[4][2], bl[4][2];
            #pragma unroll
            for (int t = 0; t < 4; t++) {
                const int r = wm * 64 + t * 16 + (lane >> 2);
                ah[t][0] = pAh[r * ROW_W + wc];
                ah[t][1] = pAh[(r + 8) * ROW_W + wc];
                ah[t][2] = pAh[r * ROW_W + wc + 4];
                ah[t][3] = pAh[(r + 8) * ROW_W + wc + 4];
                al[t][0] = pAl[r * ROW_W + wc];
                al[t][1] = pAl[(r + 8) * ROW_W + wc];
                al[t][2] = pAl[r * ROW_W + wc + 4];
                al[t][3] = pAl[(r + 8) * ROW_W + wc + 4];
            }
            #pragma unroll
            for (int n = 0; n < 4; n++) {
                const int b = wn * 32 + n * 8 + (lane >> 2);
                bh[n][0] = pBh[b * ROW_W + wc];
                bh[n][1] = pBh[b * ROW_W + wc + 4];
                bl[n][0] = pBl[b * ROW_W + wc];
                bl[n][1] = pBl[b * ROW_W + wc + 4];
            }
            #pragma unroll
            for (int t = 0; t < 4; t++)
                #pragma unroll
                for (int n = 0; n < 4; n++) {
                    MMA(acc[t][n], ah[t], bh[n]);
                    MMA(acc[t][n], ah[t], bl[n]);
                    MMA(acc[t][n], al[t], bh[n]);
                }
        }
        __syncthreads();
    }

    // epilogue
    #pragma unroll
    for (int t = 0; t < 4; t++) {
        const int r0 = rowBase + wm * 64 + t * 16 + (lane >> 2);
        #pragma unroll
        for (int n = 0; n < 4; n++) {
            const int c0 = colBase + wn * 32 + n * 8 + (lane & 3) * 2;
            float bx = 0.f, by = 0.f;
            if (BIAS) { bx = bias[c0]; by = bias[c0 + 1]; }
            float2 v0, v1;
            v0.x = acc[t][n][0] * alpha + bx;  v0.y = acc[t][n][1] * alpha + by;
            v1.x = acc[t][n][2] * alpha + bx;  v1.y = acc[t][n][3] * alpha + by;
            *(float2*)&C[(long long)r0 * ldc + c0]       = v0;
            *(float2*)&C[(long long)(r0 + 8) * ldc + c0] = v1;
        }
    }
}

// ---------------------------------------------------------------------------
// fp32 -> bf16 hi/lo split conversion (strided gather)
// ---------------------------------------------------------------------------
__global__ void conv_split(const float* __restrict__ in,
                           __nv_bfloat16* __restrict__ ohi, __nv_bfloat16* __restrict__ olo,
                           long long irs, long long izs, int R, int C)
{
    const long long idx = (long long)blockIdx.x * blockDim.x + threadIdx.x;
    const int c = (int)(idx % C);
    const int r = (int)((idx / C) % R);
    const int z = (int)(idx / ((long long)C * R));
    const float v = in[(long long)z * izs + (long long)r * irs + c];
    const __nv_bfloat16 hi = __float2bfloat16(v);
    const __nv_bfloat16 lo = __float2bfloat16(v - __bfloat162float(hi));
    ohi[idx] = hi; olo[idx] = lo;
}

// ---------------------------------------------------------------------------
// fp32 -> bf16 hi/lo transpose conversion: out[z][c][r] = in[z][r][c]
// ---------------------------------------------------------------------------
__global__ void tconv_split(const float* __restrict__ in,
                            __nv_bfloat16* __restrict__ ohi, __nv_bfloat16* __restrict__ olo,
                            long long irs, long long izs, long long ozs, int R, int C)
{
    __shared__ float t[32][33];
    const int z  = blockIdx.z;
    const int r0 = blockIdx.y * 32;
    const int c0 = blockIdx.x * 32;
    #pragma unroll
    for (int i = 0; i < 4; i++) {
        const int r = r0 + threadIdx.y + i * 8;
        t[threadIdx.y + i * 8][threadIdx.x] =
            in[(long long)z * izs + (long long)r * irs + c0 + threadIdx.x];
    }
    __syncthreads();
    #pragma unroll
    for (int i = 0; i < 4; i++) {
        const int oc  = c0 + threadIdx.y + i * 8;
        const int orr = r0 + threadIdx.x;
        const float v = t[threadIdx.x][threadIdx.y + i * 8];
        const __nv_bfloat16 hi = __float2bfloat16(v);
        const __nv_bfloat16 lo = __float2bfloat16(v - __bfloat162float(hi));
        const long long o = (long long)z * ozs + (long long)oc * R + orr;
        ohi[o] = hi; olo[o] = lo;
    }
}

// ---------------------------------------------------------------------------
// RoPE in place on fp32 mixed
// ---------------------------------------------------------------------------
__global__ void rope_kernel(float* __restrict__ mixed)
{
    const int idx = blockIdx.x * blockDim.x + threadIdx.x;
    const int i  = idx & 15;
    const int qk = (idx >> 4) & 1;
    const int h  = (idx >> 5) & 31;
    const int s  = idx >> 10;
    if (s >= SEQ) return;

    const double invd = pow(10000.0, -(double)i / 16.0);
    const float freq = (float)s * (float)invd;
    const double fd = (double)freq;
    const float c  = (float)cos(fd);
    const float sn = (float)sin(fd);

    float* p = mixed + (long long)s * QKV_N + h * 384 + qk * HD;
    const float x1 = p[i];
    const float x2 = p[i + 16];
    p[i]      = x1 * c - x2 * sn;
    p[i + 16] = x2 * c + x1 * sn;
}

// ---------------------------------------------------------------------------
// Causal softmax: fp32 scores row -> P bf16 hi/lo planes.
// ---------------------------------------------------------------------------
__device__ __forceinline__ float warpMax(float v) {
    #pragma unroll
    for (int o = 16; o; o >>= 1) v = fmaxf(v, __shfl_xor_sync(0xffffffffu, v, o));
    return v;
}
__device__ __forceinline__ float warpSum(float v) {
    #pragma unroll
    for (int o = 16; o; o >>= 1) v += __shfl_xor_sync(0xffffffffu, v, o);
    return v;
}

__global__ void __launch_bounds__(256)
softmax_kernel(const float* __restrict__ S,
               __nv_bfloat16* __restrict__ Phi, __nv_bfloat16* __restrict__ Plo)
{
    const long long row = blockIdx.x;
    const int r = (int)(row & (SEQ - 1));
    const int ncols = (((r >> 7) + 1) << 7);
    const float* p = S + row * SEQ;
    const int tid = threadIdx.x, lane = tid & 31, warp = tid >> 5;
    __shared__ float red[8];

    float m = -1e30f;
    for (int col = tid; col < ncols; col += 256)
        if (col <= r) m = fmaxf(m, p[col]);
    m = warpMax(m);
    if (lane == 0) red[warp] = m;
    __syncthreads();
    if (warp == 0) {
        float t = (lane < 8) ? red[lane] : -1e30f;
        t = warpMax(t);
        if (lane == 0) red[0] = t;
    }
    __syncthreads();
    m = red[0];
    __syncthreads();

    float sum = 0.f;
    for (int col = tid; col < ncols; col += 256)
        if (col <= r) sum += expf(p[col] - m);
    sum = warpSum(sum);
    if (lane == 0) red[warp] = sum;
    __syncthreads();
    if (warp == 0) {
        float t = (lane < 8) ? red[lane] : 0.f;
        t = warpSum(t);
        if (lane == 0) red[0] = t;
    }
    __syncthreads();
    const float inv = 1.f / red[0];

    __nv_bfloat16* ph = Phi + row * SEQ;
    __nv_bfloat16* pl = Plo + row * SEQ;
    for (int col = tid; col < ncols; col += 256) {
        float v = (col <= r) ? expf(p[col] - m) * inv : 0.f;
        const __nv_bfloat16 hi = __float2bfloat16(v);
        ph[col] = hi;
        pl[col] = __float2bfloat16(v - __bfloat162float(hi));
    }
}

// ---------------------------------------------------------------------------
// Launcher
// ---------------------------------------------------------------------------
extern "C" void kernel_launch(void* const* d_in, const int* in_sizes, int n_in,
                              void* d_out, int out_size)
{
    const float* hidden  = (const float*)d_in[0];
    const float* W_qkv   = (const float*)d_in[2];
    const float* b_qkv   = (const float*)d_in[3];
    const float* W_dense = (const float*)d_in[4];
    const float* b_dense = (const float*)d_in[5];
    float* out = (float*)d_out;

    float *mixed, *scores, *ctx;
    cudaGetSymbolAddress((void**)&mixed,  g_mixed);
    cudaGetSymbolAddress((void**)&scores, g_scores);
    cudaGetSymbolAddress((void**)&ctx,    g_ctx);
    __nv_bfloat16 *hidHi, *hidLo, *wqkvHi, *wqkvLo, *qHi, *qLo, *kHi, *kLo;
    __nv_bfloat16 *vtHi, *vtLo, *pHi, *pLo, *ctxHi, *ctxLo, *wdHi, *wdLo;
    cudaGetSymbolAddress((void**)&hidHi, g_hidHi);   cudaGetSymbolAddress((void**)&hidLo, g_hidLo);
    cudaGetSymbolAddress((void**)&wqkvHi, g_wqkvHi); cudaGetSymbolAddress((void**)&wqkvLo, g_wqkvLo);
    cudaGetSymbolAddress((void**)&qHi, g_qHi);       cudaGetSymbolAddress((void**)&qLo, g_qLo);
    cudaGetSymbolAddress((void**)&kHi, g_kHi);       cudaGetSymbolAddress((void**)&kLo, g_kLo);
    cudaGetSymbolAddress((void**)&vtHi, g_vtHi);     cudaGetSymbolAddress((void**)&vtLo, g_vtLo);
    cudaGetSymbolAddress((void**)&pHi, g_pHi);       cudaGetSymbolAddress((void**)&pLo, g_pLo);
    cudaGetSymbolAddress((void**)&ctxHi, g_ctxHi);   cudaGetSymbolAddress((void**)&ctxLo, g_ctxLo);
    cudaGetSymbolAddress((void**)&wdHi, g_wdHi);     cudaGetSymbolAddress((void**)&wdLo, g_wdLo);

    cudaFuncSetAttribute(mma_gemm<true,  false, false>, cudaFuncAttributeMaxDynamicSharedMemorySize, SMEM_TOTAL);
    cudaFuncSetAttribute(mma_gemm<false, false, true >, cudaFuncAttributeMaxDynamicSharedMemorySize, SMEM_TOTAL);
    cudaFuncSetAttribute(mma_gemm<false, true,  false>, cudaFuncAttributeMaxDynamicSharedMemorySize, SMEM_TOTAL);

    const float inv_sqrt_hd = 0.08838834764831845f;

    // conversions independent of mixed
    conv_split<<<(SEQ * HIDDEN) / 256, 256>>>(hidden, hidHi, hidLo, HIDDEN, 0, SEQ, HIDDEN);
    tconv_split<<<dim3(QKV_N / 32, HIDDEN / 32, 1), dim3(32, 8)>>>(
        W_qkv, wqkvHi, wqkvLo, QKV_N, 0, 0, HIDDEN, QKV_N);
    tconv_split<<<dim3(HIDDEN / 32, HIDDEN / 32, 1), dim3(32, 8)>>>(
        W_dense, wdHi, wdLo, HIDDEN, 0, 0, HIDDEN, HIDDEN);

    // 1) QKV GEMM
    mma_gemm<true, false, false><<<dim3(QKV_N / 128, SEQ / 128, 1), 256, SMEM_TOTAL>>>(
        hidHi, hidLo, wqkvHi, wqkvLo, b_qkv, mixed,
        HIDDEN, HIDDEN, HIDDEN, QKV_N, 0, 0, 0, 1.f);

    // 2) RoPE
    rope_kernel<<<(SEQ * NHEADS * 2 * 16) / 256, 256>>>(mixed);

    // 3) per-head Q/K/V plane conversions
    conv_split<<<(NHEADS * SEQ * HD) / 256, 256>>>(mixed,       qHi, qLo, QKV_N, 384, SEQ, HD);
    conv_split<<<(NHEADS * SEQ * HD) / 256, 256>>>(mixed + 128, kHi, kLo, QKV_N, 384, SEQ, HD);
    tconv_split<<<dim3(HD / 32, SEQ / 32, NHEADS), dim3(32, 8)>>>(
        mixed + 256, vtHi, vtLo, QKV_N, 384, (long long)HD * SEQ, SEQ, HD);

    // 4) scores = (Q @ K^T) / sqrt(HD), lower+diag tiles only
    mma_gemm<false, false, true><<<dim3(SEQ / 128, SEQ / 128, NHEADS), 256, SMEM_TOTAL>>>(
        qHi, qLo, kHi, kLo, nullptr, scores,
        HD, HD, HD, SEQ,
        (long long)SEQ * HD, (long long)SEQ * HD, (long long)SEQ * SEQ, inv_sqrt_hd);

    // 5) causal softmax -> P hi/lo planes
    softmax_kernel<<<NHEADS * SEQ, 256>>>(scores, pHi, pLo);

    // 6) ctx = P @ V (K limited to rowBase+128)
    mma_gemm<false, true, false><<<dim3(1, SEQ / 128, NHEADS), 256, SMEM_TOTAL>>>(
        pHi, pLo, vtHi, vtLo, nullptr, ctx,
        SEQ, SEQ, SEQ, HIDDEN,
        (long long)SEQ * SEQ, (long long)HD * SEQ, HD, 1.f);

    // 7) ctx conversion + dense GEMM
    conv_split<<<(SEQ * HIDDEN) / 256, 256>>>(ctx, ctxHi, ctxLo, HIDDEN, 0, SEQ, HIDDEN);
    mma_gemm<true, false, false><<<dim3(HIDDEN / 128, SEQ / 128, 1), 256, SMEM_TOTAL>>>(
        ctxHi, ctxLo, wdHi, wdLo, b_dense, out,
        HIDDEN, HIDDEN, HIDDEN, HIDDEN, 0, 0, 0, 1.f);
}

// round 5
// speedup vs baseline: 2.4884x; 1.1636x over previous
#include <cuda_runtime.h>
#include <cuda_bf16.h>
#include <math.h>
#include <stdint.h>

#define SEQ     2048
#define HIDDEN  4096
#define NHEADS  32
#define HD      128
#define QKV_N   12288

// ---------------------------------------------------------------------------
// Scratch (device globals; no allocation allowed in kernel_launch)
// ---------------------------------------------------------------------------
__device__ float g_mixed[SEQ * QKV_N];
__device__ float g_scores[(long long)NHEADS * SEQ * SEQ];
__device__ float g_ctx[SEQ * HIDDEN];

__device__ __align__(256) __nv_bfloat16 g_hidHi[SEQ * HIDDEN];
__device__ __align__(256) __nv_bfloat16 g_hidLo[SEQ * HIDDEN];
__device__ __align__(256) __nv_bfloat16 g_wqkvHi[(long long)QKV_N * HIDDEN]; // W_qkv^T [n][k]
__device__ __align__(256) __nv_bfloat16 g_wqkvLo[(long long)QKV_N * HIDDEN];
__device__ __align__(256) __nv_bfloat16 g_qHi[NHEADS * SEQ * HD];
__device__ __align__(256) __nv_bfloat16 g_qLo[NHEADS * SEQ * HD];
__device__ __align__(256) __nv_bfloat16 g_kHi[NHEADS * SEQ * HD];
__device__ __align__(256) __nv_bfloat16 g_kLo[NHEADS * SEQ * HD];
__device__ __align__(256) __nv_bfloat16 g_vtHi[NHEADS * HD * SEQ];          // V^T [h][d][t]
__device__ __align__(256) __nv_bfloat16 g_vtLo[NHEADS * HD * SEQ];
__device__ __align__(256) __nv_bfloat16 g_pHi[(long long)NHEADS * SEQ * SEQ];
__device__ __align__(256) __nv_bfloat16 g_pLo[(long long)NHEADS * SEQ * SEQ];
__device__ __align__(256) __nv_bfloat16 g_ctxHi[SEQ * HIDDEN];
__device__ __align__(256) __nv_bfloat16 g_ctxLo[SEQ * HIDDEN];
__device__ __align__(256) __nv_bfloat16 g_wdHi[HIDDEN * HIDDEN];            // W_dense^T
__device__ __align__(256) __nv_bfloat16 g_wdLo[HIDDEN * HIDDEN];

// ---------------------------------------------------------------------------
// Helpers (all plain sm_80-class PTX: cp.async + mma.sync + ldmatrix)
// ---------------------------------------------------------------------------
__device__ __forceinline__ uint32_t smem_u32(const void* p) {
    uint32_t a;
    asm("{ .reg .u64 t; cvta.to.shared.u64 t, %1; cvt.u32.u64 %0, t; }" : "=r"(a) : "l"(p));
    return a;
}
#define CPA16(dst, src)  asm volatile("cp.async.cg.shared.global [%0], [%1], 16;" :: "r"(dst), "l"(src))
#define CP_COMMIT()      asm volatile("cp.async.commit_group;" ::: "memory")
#define CP_WAIT2()       asm volatile("cp.async.wait_group 2;" ::: "memory")
#define CP_WAIT1()       asm volatile("cp.async.wait_group 1;" ::: "memory")
#define CP_WAIT0()       asm volatile("cp.async.wait_group 0;" ::: "memory")

#define MMA(d, a, b)                                                          \
    asm volatile("mma.sync.aligned.m16n8k16.row.col.f32.bf16.bf16.f32 "       \
        "{%0,%1,%2,%3}, {%4,%5,%6,%7}, {%8,%9}, {%0,%1,%2,%3};"               \
        : "+f"((d)[0]), "+f"((d)[1]), "+f"((d)[2]), "+f"((d)[3])              \
        : "r"((a)[0]), "r"((a)[1]), "r"((a)[2]), "r"((a)[3]),                 \
          "r"((b)[0]), "r"((b)[1]))

#define LDSM4(r0, r1, r2, r3, addr)                                           \
    asm volatile("ldmatrix.sync.aligned.m8n8.x4.shared.b16 {%0,%1,%2,%3}, [%4];" \
        : "=r"(r0), "=r"(r1), "=r"(r2), "=r"(r3) : "r"(addr))

// SMEM: 4 planes (Ahi, Alo, Bhi, Blo) x 128 rows x 32 bf16, padded to
// 40 bf16 (80B) per row => conflict-free LDSM. 4 stages.
#define PLANE_B   10240u                 // 128 * 80 bytes
#define STAGE_B   (4 * PLANE_B)          // 40960 B
#define SMEM_TOTAL (4 * STAGE_B)         // 163840 B

// ---------------------------------------------------------------------------
// Split-bf16 GEMM via mma.sync: C[M,N] = alpha * A[M,K] @ B[N,K]^T (+bias)
// 128x128 tile, BK=32, 4-stage cp.async, ldmatrix fragments.
// ---------------------------------------------------------------------------
template <bool BIAS, bool CAUSALK, bool SKIPUPPER>
__global__ void __launch_bounds__(256, 1)
mma_gemm(const __nv_bfloat16* __restrict__ Ahi, const __nv_bfloat16* __restrict__ Alo,
         const __nv_bfloat16* __restrict__ Bhi, const __nv_bfloat16* __restrict__ Blo,
         const float* __restrict__ bias, float* __restrict__ C,
         int K, int lda, int ldb, int ldc,
         long long azs, long long bzs, long long czs, float alpha)
{
    extern __shared__ char smem[];
    const int tid = threadIdx.x;
    const int rowBase = blockIdx.y * 128;
    const int colBase = blockIdx.x * 128;
    if (SKIPUPPER && colBase > rowBase) return;

    const int z = blockIdx.z;
    Ahi += (long long)z * azs;  Alo += (long long)z * azs;
    Bhi += (long long)z * bzs;  Blo += (long long)z * bzs;
    C   += (long long)z * czs;

    const int kEnd  = CAUSALK ? min(K, rowBase + 128) : K;
    const int niter = kEnd >> 5;

    const uint32_t sbase = smem_u32(smem);
    const int lane = tid & 31;
    const int wid  = tid >> 5;
    const int wm   = wid & 1;    // 0..1  -> 64-row slice
    const int wn   = wid >> 1;   // 0..3  -> 32-col slice

    // lane constants for ldmatrix addressing (bytes)
    const uint32_t laneA = (uint32_t)(((lane & 7) + ((lane >> 3) & 1) * 8) * 80
                                      + (lane >> 4) * 16);
    const uint32_t laneB = (uint32_t)(((lane & 7) + (lane >> 4) * 8) * 80
                                      + ((lane >> 3) & 1) * 16);
    const uint32_t aRowOff = (uint32_t)(wm * 64) * 80u;
    const uint32_t bRowOff = (uint32_t)(wn * 32) * 80u;

    float acc[4][4][4] = {};

    // 2048 x 16B chunks per stage, 8 per thread
    auto issue = [&](int i) {
        const int s  = i & 3;
        const int k0 = i << 5;
        #pragma unroll
        for (int j = 0; j < 8; j++) {
            const int c     = j * 256 + tid;
            const int plane = c >> 9;
            const int rem   = c & 511;
            const int row   = rem >> 2;
            const int seg   = rem & 3;
            const uint32_t dst = sbase + (uint32_t)s * STAGE_B + (uint32_t)plane * PLANE_B
                               + (uint32_t)row * 80u + (uint32_t)seg * 16u;
            const __nv_bfloat16* src;
            if (plane == 0)      src = Ahi + (long long)(rowBase + row) * lda + k0 + seg * 8;
            else if (plane == 1) src = Alo + (long long)(rowBase + row) * lda + k0 + seg * 8;
            else if (plane == 2) src = Bhi + (long long)(colBase + row) * ldb + k0 + seg * 8;
            else                 src = Blo + (long long)(colBase + row) * ldb + k0 + seg * 8;
            CPA16(dst, src);
        }
        CP_COMMIT();
    };

    issue(0);
    if (niter > 1) issue(1);

    for (int i = 0; i < niter; i++) {
        if (i + 2 < niter) { issue(i + 2); CP_WAIT2(); }
        else if (i + 1 < niter) CP_WAIT1();
        else CP_WAIT0();
        __syncthreads();

        const uint32_t st  = sbase + (uint32_t)(i & 3) * STAGE_B;
        const uint32_t pAh = st;
        const uint32_t pAl = st + PLANE_B;
        const uint32_t pBh = st + 2 * PLANE_B;
        const uint32_t pBl = st + 3 * PLANE_B;

        #pragma unroll
        for (int kk = 0; kk < 2; kk++) {
            const uint32_t kOff = (uint32_t)kk * 32u;
            uint32_t bh[4][2], bl[4][2];
            LDSM4(bh[0][0], bh[0][1], bh[1][0], bh[1][1], pBh + bRowOff + kOff + laneB);
            LDSM4(bh[2][0], bh[2][1], bh[3][0], bh[3][1], pBh + bRowOff + 1280u + kOff + laneB);
            LDSM4(bl[0][0], bl[0][1], bl[1][0], bl[1][1], pBl + bRowOff + kOff + laneB);
            LDSM4(bl[2][0], bl[2][1], bl[3][0], bl[3][1], pBl + bRowOff + 1280u + kOff + laneB);

            #pragma unroll
            for (int t = 0; t < 4; t++) {
                uint32_t ah[4], al[4];
                const uint32_t tOff = aRowOff + (uint32_t)t * 1280u + kOff;
                LDSM4(ah[0], ah[1], ah[2], ah[3], pAh + tOff + laneA);
                LDSM4(al[0], al[1], al[2], al[3], pAl + tOff + laneA);
                #pragma unroll
                for (int n = 0; n < 4; n++) {
                    MMA(acc[t][n], ah, bh[n]);
                    MMA(acc[t][n], ah, bl[n]);
                    MMA(acc[t][n], al, bh[n]);
                }
            }
        }
        // no trailing barrier: stage (i+2)&3 written at iter i was consumed at
        // iter i-2; sync at iter i already fences all warps past compute(i-1).
    }

    // epilogue
    #pragma unroll
    for (int t = 0; t < 4; t++) {
        const int r0 = rowBase + wm * 64 + t * 16 + (lane >> 2);
        #pragma unroll
        for (int n = 0; n < 4; n++) {
            const int c0 = colBase + wn * 32 + n * 8 + (lane & 3) * 2;
            float bx = 0.f, by = 0.f;
            if (BIAS) { bx = bias[c0]; by = bias[c0 + 1]; }
            float2 v0, v1;
            v0.x = acc[t][n][0] * alpha + bx;  v0.y = acc[t][n][1] * alpha + by;
            v1.x = acc[t][n][2] * alpha + bx;  v1.y = acc[t][n][3] * alpha + by;
            *(float2*)&C[(long long)r0 * ldc + c0]       = v0;
            *(float2*)&C[(long long)(r0 + 8) * ldc + c0] = v1;
        }
    }
}

// ---------------------------------------------------------------------------
// fp32 -> bf16 hi/lo split conversion (strided gather)
// ---------------------------------------------------------------------------
__global__ void conv_split(const float* __restrict__ in,
                           __nv_bfloat16* __restrict__ ohi, __nv_bfloat16* __restrict__ olo,
                           long long irs, long long izs, int R, int C)
{
    const long long idx = (long long)blockIdx.x * blockDim.x + threadIdx.x;
    const int c = (int)(idx % C);
    const int r = (int)((idx / C) % R);
    const int z = (int)(idx / ((long long)C * R));
    const float v = in[(long long)z * izs + (long long)r * irs + c];
    const __nv_bfloat16 hi = __float2bfloat16(v);
    const __nv_bfloat16 lo = __float2bfloat16(v - __bfloat162float(hi));
    ohi[idx] = hi; olo[idx] = lo;
}

// ---------------------------------------------------------------------------
// fp32 -> bf16 hi/lo transpose conversion: out[z][c][r] = in[z][r][c]
// ---------------------------------------------------------------------------
__global__ void tconv_split(const float* __restrict__ in,
                            __nv_bfloat16* __restrict__ ohi, __nv_bfloat16* __restrict__ olo,
                            long long irs, long long izs, long long ozs, int R, int C)
{
    __shared__ float t[32][33];
    const int z  = blockIdx.z;
    const int r0 = blockIdx.y * 32;
    const int c0 = blockIdx.x * 32;
    #pragma unroll
    for (int i = 0; i < 4; i++) {
        const int r = r0 + threadIdx.y + i * 8;
        t[threadIdx.y + i * 8][threadIdx.x] =
            in[(long long)z * izs + (long long)r * irs + c0 + threadIdx.x];
    }
    __syncthreads();
    #pragma unroll
    for (int i = 0; i < 4; i++) {
        const int oc  = c0 + threadIdx.y + i * 8;
        const int orr = r0 + threadIdx.x;
        const float v = t[threadIdx.x][threadIdx.y + i * 8];
        const __nv_bfloat16 hi = __float2bfloat16(v);
        const __nv_bfloat16 lo = __float2bfloat16(v - __bfloat162float(hi));
        const long long o = (long long)z * ozs + (long long)oc * R + orr;
        ohi[o] = hi; olo[o] = lo;
    }
}

// ---------------------------------------------------------------------------
// RoPE in place on fp32 mixed
// ---------------------------------------------------------------------------
__global__ void rope_kernel(float* __restrict__ mixed)
{
    const int idx = blockIdx.x * blockDim.x + threadIdx.x;
    const int i  = idx & 15;
    const int qk = (idx >> 4) & 1;
    const int h  = (idx >> 5) & 31;
    const int s  = idx >> 10;
    if (s >= SEQ) return;

    const double invd = pow(10000.0, -(double)i / 16.0);
    const float freq = (float)s * (float)invd;
    const double fd = (double)freq;
    const float c  = (float)cos(fd);
    const float sn = (float)sin(fd);

    float* p = mixed + (long long)s * QKV_N + h * 384 + qk * HD;
    const float x1 = p[i];
    const float x2 = p[i + 16];
    p[i]      = x1 * c - x2 * sn;
    p[i + 16] = x2 * c + x1 * sn;
}

// ---------------------------------------------------------------------------
// Causal softmax: fp32 scores row -> P bf16 hi/lo planes.
// ---------------------------------------------------------------------------
__device__ __forceinline__ float warpMax(float v) {
    #pragma unroll
    for (int o = 16; o; o >>= 1) v = fmaxf(v, __shfl_xor_sync(0xffffffffu, v, o));
    return v;
}
__device__ __forceinline__ float warpSum(float v) {
    #pragma unroll
    for (int o = 16; o; o >>= 1) v += __shfl_xor_sync(0xffffffffu, v, o);
    return v;
}

__global__ void __launch_bounds__(256)
softmax_kernel(const float* __restrict__ S,
               __nv_bfloat16* __restrict__ Phi, __nv_bfloat16* __restrict__ Plo)
{
    const long long row = blockIdx.x;
    const int r = (int)(row & (SEQ - 1));
    const int ncols = (((r >> 7) + 1) << 7);
    const float* p = S + row * SEQ;
    const int tid = threadIdx.x, lane = tid & 31, warp = tid >> 5;
    __shared__ float red[8];

    float m = -1e30f;
    for (int col = tid; col < ncols; col += 256)
        if (col <= r) m = fmaxf(m, p[col]);
    m = warpMax(m);
    if (lane == 0) red[warp] = m;
    __syncthreads();
    if (warp == 0) {
        float t = (lane < 8) ? red[lane] : -1e30f;
        t = warpMax(t);
        if (lane == 0) red[0] = t;
    }
    __syncthreads();
    m = red[0];
    __syncthreads();

    float sum = 0.f;
    for (int col = tid; col < ncols; col += 256)
        if (col <= r) sum += expf(p[col] - m);
    sum = warpSum(sum);
    if (lane == 0) red[warp] = sum;
    __syncthreads();
    if (warp == 0) {
        float t = (lane < 8) ? red[lane] : 0.f;
        t = warpSum(t);
        if (lane == 0) red[0] = t;
    }
    __syncthreads();
    const float inv = 1.f / red[0];

    __nv_bfloat16* ph = Phi + row * SEQ;
    __nv_bfloat16* pl = Plo + row * SEQ;
    for (int col = tid; col < ncols; col += 256) {
        float v = (col <= r) ? expf(p[col] - m) * inv : 0.f;
        const __nv_bfloat16 hi = __float2bfloat16(v);
        ph[col] = hi;
        pl[col] = __float2bfloat16(v - __bfloat162float(hi));
    }
}

// ---------------------------------------------------------------------------
// Launcher
// ---------------------------------------------------------------------------
extern "C" void kernel_launch(void* const* d_in, const int* in_sizes, int n_in,
                              void* d_out, int out_size)
{
    const float* hidden  = (const float*)d_in[0];
    const float* W_qkv   = (const float*)d_in[2];
    const float* b_qkv   = (const float*)d_in[3];
    const float* W_dense = (const float*)d_in[4];
    const float* b_dense = (const float*)d_in[5];
    float* out = (float*)d_out;

    float *mixed, *scores, *ctx;
    cudaGetSymbolAddress((void**)&mixed,  g_mixed);
    cudaGetSymbolAddress((void**)&scores, g_scores);
    cudaGetSymbolAddress((void**)&ctx,    g_ctx);
    __nv_bfloat16 *hidHi, *hidLo, *wqkvHi, *wqkvLo, *qHi, *qLo, *kHi, *kLo;
    __nv_bfloat16 *vtHi, *vtLo, *pHi, *pLo, *ctxHi, *ctxLo, *wdHi, *wdLo;
    cudaGetSymbolAddress((void**)&hidHi, g_hidHi);   cudaGetSymbolAddress((void**)&hidLo, g_hidLo);
    cudaGetSymbolAddress((void**)&wqkvHi, g_wqkvHi); cudaGetSymbolAddress((void**)&wqkvLo, g_wqkvLo);
    cudaGetSymbolAddress((void**)&qHi, g_qHi);       cudaGetSymbolAddress((void**)&qLo, g_qLo);
    cudaGetSymbolAddress((void**)&kHi, g_kHi);       cudaGetSymbolAddress((void**)&kLo, g_kLo);
    cudaGetSymbolAddress((void**)&vtHi, g_vtHi);     cudaGetSymbolAddress((void**)&vtLo, g_vtLo);
    cudaGetSymbolAddress((void**)&pHi, g_pHi);       cudaGetSymbolAddress((void**)&pLo, g_pLo);
    cudaGetSymbolAddress((void**)&ctxHi, g_ctxHi);   cudaGetSymbolAddress((void**)&ctxLo, g_ctxLo);
    cudaGetSymbolAddress((void**)&wdHi, g_wdHi);     cudaGetSymbolAddress((void**)&wdLo, g_wdLo);

    cudaFuncSetAttribute(mma_gemm<true,  false, false>, cudaFuncAttributeMaxDynamicSharedMemorySize, SMEM_TOTAL);
    cudaFuncSetAttribute(mma_gemm<false, false, true >, cudaFuncAttributeMaxDynamicSharedMemorySize, SMEM_TOTAL);
    cudaFuncSetAttribute(mma_gemm<false, true,  false>, cudaFuncAttributeMaxDynamicSharedMemorySize, SMEM_TOTAL);

    const float inv_sqrt_hd = 0.08838834764831845f;

    // conversions independent of mixed
    conv_split<<<(SEQ * HIDDEN) / 256, 256>>>(hidden, hidHi, hidLo, HIDDEN, 0, SEQ, HIDDEN);
    tconv_split<<<dim3(QKV_N / 32, HIDDEN / 32, 1), dim3(32, 8)>>>(
        W_qkv, wqkvHi, wqkvLo, QKV_N, 0, 0, HIDDEN, QKV_N);
    tconv_split<<<dim3(HIDDEN / 32, HIDDEN / 32, 1), dim3(32, 8)>>>(
        W_dense, wdHi, wdLo, HIDDEN, 0, 0, HIDDEN, HIDDEN);

    // 1) QKV GEMM
    mma_gemm<true, false, false><<<dim3(QKV_N / 128, SEQ / 128, 1), 256, SMEM_TOTAL>>>(
        hidHi, hidLo, wqkvHi, wqkvLo, b_qkv, mixed,
        HIDDEN, HIDDEN, HIDDEN, QKV_N, 0, 0, 0, 1.f);

    // 2) RoPE
    rope_kernel<<<(SEQ * NHEADS * 2 * 16) / 256, 256>>>(mixed);

    // 3) per-head Q/K/V plane conversions
    conv_split<<<(NHEADS * SEQ * HD) / 256, 256>>>(mixed,       qHi, qLo, QKV_N, 384, SEQ, HD);
    conv_split<<<(NHEADS * SEQ * HD) / 256, 256>>>(mixed + 128, kHi, kLo, QKV_N, 384, SEQ, HD);
    tconv_split<<<dim3(HD / 32, SEQ / 32, NHEADS), dim3(32, 8)>>>(
        mixed + 256, vtHi, vtLo, QKV_N, 384, (long long)HD * SEQ, SEQ, HD);

    // 4) scores = (Q @ K^T) / sqrt(HD), lower+diag tiles only
    mma_gemm<false, false, true><<<dim3(SEQ / 128, SEQ / 128, NHEADS), 256, SMEM_TOTAL>>>(
        qHi, qLo, kHi, kLo, nullptr, scores,
        HD, HD, HD, SEQ,
        (long long)SEQ * HD, (long long)SEQ * HD, (long long)SEQ * SEQ, inv_sqrt_hd);

    // 5) causal softmax -> P hi/lo planes
    softmax_kernel<<<NHEADS * SEQ, 256>>>(scores, pHi, pLo);

    // 6) ctx = P @ V (K limited to rowBase+128)
    mma_gemm<false, true, false><<<dim3(1, SEQ / 128, NHEADS), 256, SMEM_TOTAL>>>(
        pHi, pLo, vtHi, vtLo, nullptr, ctx,
        SEQ, SEQ, SEQ, HIDDEN,
        (long long)SEQ * SEQ, (long long)HD * SEQ, HD, 1.f);

    // 7) ctx conversion + dense GEMM
    conv_split<<<(SEQ * HIDDEN) / 256, 256>>>(ctx, ctxHi, ctxLo, HIDDEN, 0, SEQ, HIDDEN);
    mma_gemm<true, false, false><<<dim3(HIDDEN / 128, SEQ / 128, 1), 256, SMEM_TOTAL>>>(
        ctxHi, ctxLo, wdHi, wdLo, b_dense, out,
        HIDDEN, HIDDEN, HIDDEN, HIDDEN, 0, 0, 0, 1.f);
}